// round 15
// baseline (speedup 1.0000x reference)
#include <cuda_runtime.h>
#include <cstdint>

// Problem constants (stagenet_46445776339346): V=5, B=2, C=32, H=W=128, D=32, G=8
#define NV 5
#define NB 2
#define NC 32
#define NH 128
#define NW 128
#define ND 32
#define NG 8
#define HW (NH * NW)

// ---------------------------------------------------------------------------
// Device scratch (no runtime allocation allowed)
// ---------------------------------------------------------------------------
// packed projection: per (b,v) three float4 rows {R3r, R3r+1, R3r+2, Tr}
__device__ float4 g_proj4[NB][NV][3];
// features transposed to [V, B, H*W, C]: one bilinear tap = 128 contiguous bytes.
__device__ float4 g_featT[(size_t)NV * NB * HW * (NC / 4)];
// depth hypotheses transposed to [B, H*W, D]: one warp load = 128 contiguous B.
__device__ float  g_depT[(size_t)NB * HW * ND];

// ---------------------------------------------------------------------------
// FROZEN NUMERICS: fp32 4x4 inverse = sgetf2 LU + OpenBLAS-style trsm
// (pre-inverted diagonal). Do not touch.
// ---------------------------------------------------------------------------
__device__ void inv4_lapack_f32(const float* A_rm, float* Ai_rm) {
    float a[16];
    int   piv[4];
#pragma unroll
    for (int r = 0; r < 4; r++)
#pragma unroll
        for (int c = 0; c < 4; c++) a[c * 4 + r] = A_rm[r * 4 + c];

#pragma unroll
    for (int j = 0; j < 4; j++) {
        int jp = j; float amax = fabsf(a[j * 4 + j]);
        for (int i = j + 1; i < 4; i++) {
            float v = fabsf(a[j * 4 + i]);
            if (v > amax) { amax = v; jp = i; }
        }
        piv[j] = jp;
        if (jp != j)
#pragma unroll
            for (int c = 0; c < 4; c++) {
                float t = a[c * 4 + j]; a[c * 4 + j] = a[c * 4 + jp]; a[c * 4 + jp] = t;
            }
        float ainv = __fdiv_rn(1.0f, a[j * 4 + j]);
        for (int i = j + 1; i < 4; i++)
            a[j * 4 + i] = __fmul_rn(a[j * 4 + i], ainv);
        for (int k = j + 1; k < 4; k++) {
            float temp = -a[k * 4 + j];
            for (int i = j + 1; i < 4; i++)
                a[k * 4 + i] = fmaf(a[j * 4 + i], temp, a[k * 4 + i]);
        }
    }

    float dinv[4];
#pragma unroll
    for (int k = 0; k < 4; k++) dinv[k] = __fdiv_rn(1.0f, a[k * 4 + k]);

#pragma unroll
    for (int c = 0; c < 4; c++) {
        float b[4] = {0.f, 0.f, 0.f, 0.f};
        b[c] = 1.0f;
#pragma unroll
        for (int j = 0; j < 4; j++) { float t = b[j]; b[j] = b[piv[j]]; b[piv[j]] = t; }
#pragma unroll
        for (int k = 0; k < 4; k++) {
            float bk = b[k];
            if (bk != 0.f)
                for (int i = k + 1; i < 4; i++)
                    b[i] = fmaf(-bk, a[k * 4 + i], b[i]);
        }
#pragma unroll
        for (int k = 3; k >= 0; k--) {
            b[k] = __fmul_rn(b[k], dinv[k]);
            float bk = b[k];
            for (int i = 0; i < k; i++)
                b[i] = fmaf(-bk, a[k * 4 + i], b[i]);
        }
#pragma unroll
        for (int r = 0; r < 4; r++) Ai_rm[r * 4 + c] = b[r];
    }
}

__device__ void make_comb_f32(const float* pm, int b, int v, float* M) {
    const float* ext = pm + ((size_t)(b * NV + v) * 2 + 0) * 16;
    const float* K   = pm + ((size_t)(b * NV + v) * 2 + 1) * 16;
#pragma unroll
    for (int r = 0; r < 3; r++)
#pragma unroll
        for (int c = 0; c < 4; c++) {
            float s = __fmul_rn(K[r * 4 + 0], ext[0 * 4 + c]);
            s = fmaf(K[r * 4 + 1], ext[1 * 4 + c], s);
            s = fmaf(K[r * 4 + 2], ext[2 * 4 + c], s);
            M[r * 4 + c] = s;
        }
#pragma unroll
    for (int c = 0; c < 4; c++) M[12 + c] = ext[12 + c];
}

__device__ void do_setup(const float* pm, int b) {
    float Mr[16], Mi[16];
    make_comb_f32(pm, b, 0, Mr);
    inv4_lapack_f32(Mr, Mi);
    for (int v = 1; v < NV; v++) {
        float Ms[16];
        make_comb_f32(pm, b, v, Ms);
        float* P = (float*)&g_proj4[b][v][0];
        for (int r = 0; r < 3; r++) {
            for (int c = 0; c < 4; c++) {
                float s = __fmul_rn(Ms[r * 4 + 0], Mi[0 * 4 + c]);
                s = fmaf(Ms[r * 4 + 1], Mi[1 * 4 + c], s);
                s = fmaf(Ms[r * 4 + 2], Mi[2 * 4 + c], s);
                s = fmaf(Ms[r * 4 + 3], Mi[3 * 4 + c], s);
                // row r packed as {R3r, R3r+1, R3r+2, Tr}
                if (c < 3) P[r * 4 + c] = s;
                else       P[r * 4 + 3] = s;
            }
        }
    }
}

// ---------------------------------------------------------------------------
// Prep kernel: 32x32 float4-vectorized transposes.
//   blockIdx.y <  NV*NB : features [C, HW] -> [HW, C]
//   blockIdx.y >= NV*NB : depth    [D, HW] -> [HW, D]   (D == C == 32)
// Projection setup runs on 2 threads of block (0,0), overlapped.
// ---------------------------------------------------------------------------
__global__ void prep_kernel(const float* __restrict__ fea,
                            const float* __restrict__ dh,
                            const float* __restrict__ pm) {
    __shared__ float tile[32][33];
    int by = blockIdx.y;
    int pb = blockIdx.x * 32;
    int tx = threadIdx.x;   // 0..7
    int ty = threadIdx.y;   // 0..31

    if (blockIdx.x == 0 && by == 0 && ty == 31 && tx < NB)
        do_setup(pm, tx);

    const float* src;
    float*       dst;
    if (by < NV * NB) {
        src = fea + ((size_t)by * NC + ty) * HW + pb;
        dst = (float*)g_featT + ((size_t)by * HW + pb) * NC;
    } else {
        int b = by - NV * NB;
        src = dh + ((size_t)b * ND + ty) * HW + pb;
        dst = g_depT + ((size_t)b * HW + pb) * ND;
    }

    float4 v = ((const float4*)src)[tx];
    tile[ty][4 * tx + 0] = v.x;
    tile[ty][4 * tx + 1] = v.y;
    tile[ty][4 * tx + 2] = v.z;
    tile[ty][4 * tx + 3] = v.w;
    __syncthreads();

    float4 o;
    o.x = tile[4 * tx + 0][ty];
    o.y = tile[4 * tx + 1][ty];
    o.z = tile[4 * tx + 2][ty];
    o.w = tile[4 * tx + 3][ty];
    ((float4*)(dst + (size_t)ty * 32))[tx] = o;
}

__device__ __forceinline__ float warp_bfly_sum(float x) {
    const unsigned FULL = 0xffffffffu;
#pragma unroll
    for (int o = 16; o; o >>= 1) x = __fadd_rn(x, __shfl_xor_sync(FULL, x, o));
    return x;
}

__device__ __forceinline__ float warp_bfly_max(float x) {
    const unsigned FULL = 0xffffffffu;
#pragma unroll
    for (int o = 16; o; o >>= 1) x = fmaxf(x, __shfl_xor_sync(FULL, x, o));
    return x;
}

// Butterfly sum within each 8-lane group (offsets 1,2,4).
__device__ __forceinline__ float group8_sum(float x) {
    const unsigned FULL = 0xffffffffu;
#pragma unroll
    for (int o = 1; o < 8; o <<= 1) x = __fadd_rn(x, __shfl_xor_sync(FULL, x, o));
    return x;
}

// ---------------------------------------------------------------------------
// Main kernel: one warp per ref pixel, lane = depth hypothesis.
// ---------------------------------------------------------------------------
__global__ void __launch_bounds__(128, 10) stagenet_main(
    const float* __restrict__ reg_w,
    float* __restrict__ out) {
    const unsigned FULL = 0xffffffffu;
    __shared__ float4 rf_s[4][8];
    __shared__ float  attn_s[4][40];   // stride 40: conflict-free both ways

    int warp = blockIdx.x * (blockDim.x >> 5) + (threadIdx.x >> 5);
    int wslot = threadIdx.x >> 5;
    int lane = threadIdx.x & 31;
    int gl   = lane & 7;

    int b  = warp >> 14;
    int hw = warp & (HW - 1);
    int h  = hw >> 7;
    int w  = hw & (NW - 1);

    if (lane < 8)
        rf_s[wslot][lane] = __ldg(g_featT + ((unsigned)b * HW + hw) * 8 + lane);
    __syncwarp();
    float4 rfl = rf_s[wslot][gl];
    float  rw_l = __ldg(reg_w + gl);

    // transposed depth: 32 consecutive floats per warp = 1 cache line
    float dep = g_depT[((unsigned)b * HW + hw) * ND + lane];
    float xw = (float)w, yh = (float)h;

    float s_v[NV - 1], r_v[NV - 1];

#pragma unroll
    for (int vi = 0; vi < NV - 1; vi++) {
        int v = vi + 1;
        // packed projection rows: {R0,R1,R2,T0} {R3,R4,R5,T1} {R6,R7,R8,T2}
        float4 P0 = g_proj4[b][v][0];
        float4 P1 = g_proj4[b][v][1];
        float4 P2 = g_proj4[b][v][2];
        float rx = fmaf(P0.z, 1.f, fmaf(P0.y, yh, __fmul_rn(P0.x, xw)));
        float ry = fmaf(P1.z, 1.f, fmaf(P1.y, yh, __fmul_rn(P1.x, xw)));
        float rz = fmaf(P2.z, 1.f, fmaf(P2.y, yh, __fmul_rn(P2.x, xw)));
        float X = __fadd_rn(__fmul_rn(rx, dep), P0.w);
        float Y = __fadd_rn(__fmul_rn(ry, dep), P1.w);
        float Z = __fadd_rn(__fmul_rn(rz, dep), P2.w);
        if (Z == 0.f) Z = 1e-9f;
        float px = __fdiv_rn(X, Z);
        float py = __fdiv_rn(Y, Z);

        float x0f = floorf(px), y0f = floorf(py);
        int   x0 = (int)x0f,   y0 = (int)y0f;
        float wx1 = __fsub_rn(px, x0f), wx0 = __fsub_rn(1.f, wx1);
        float wy1 = __fsub_rn(py, y0f), wy0 = __fsub_rn(1.f, wy1);

        int x0c = min(max(x0, 0), NW - 1), x1c = min(max(x0 + 1, 0), NW - 1);
        int y0c = min(max(y0, 0), NH - 1), y1c = min(max(y0 + 1, 0), NH - 1);
        bool vx0 = (x0 >= 0) & (x0 < NW),     vx1 = (x0 + 1 >= 0) & (x0 + 1 < NW);
        bool vy0 = (y0 >= 0) & (y0 < NH),     vy1 = (y0 + 1 >= 0) & (y0 + 1 < NH);
        float wts[4] = {
            (vx0 & vy0) ? __fmul_rn(wx0, wy0) : 0.f,
            (vx1 & vy0) ? __fmul_rn(wx1, wy0) : 0.f,
            (vx0 & vy1) ? __fmul_rn(wx0, wy1) : 0.f,
            (vx1 & vy1) ? __fmul_rn(wx1, wy1) : 0.f };
        const float4* base = g_featT + (unsigned)(v * NB + b) * (HW * 8u);

        // single-key uniformity check (x0, y0 both small integers)
        int key = (y0 << 16) ^ (x0 & 0xffff);
        bool uni = __all_sync(FULL, key == __shfl_sync(FULL, key, 0));

        float s, r;
        if (uni) {
            int xc = (lane & 8)  ? x1c : x0c;
            int yc = (lane & 16) ? y1c : y0c;
            float4 q = __ldg(base + (unsigned)(yc * NW + xc) * 8u + (unsigned)gl);
            float d = fmaf(q.x, rfl.x,
                      fmaf(q.y, rfl.y,
                      fmaf(q.z, rfl.z, __fmul_rn(q.w, rfl.w))));
            float D  = group8_sum(d);                       // sum_g d[t,g]
            float Dr = group8_sum(__fmul_rn(rw_l, d));      // sum_g rw_g*d[t,g]
            float D0  = __shfl_sync(FULL, D, 0),  D1  = __shfl_sync(FULL, D, 8);
            float D2  = __shfl_sync(FULL, D, 16), D3  = __shfl_sync(FULL, D, 24);
            float Dr0 = __shfl_sync(FULL, Dr, 0),  Dr1 = __shfl_sync(FULL, Dr, 8);
            float Dr2 = __shfl_sync(FULL, Dr, 16), Dr3 = __shfl_sync(FULL, Dr, 24);
            s = __fmul_rn(0.25f, fmaf(wts[3], D3, fmaf(wts[2], D2,
                          fmaf(wts[1], D1, __fmul_rn(wts[0], D0)))));
            r = __fmul_rn(0.25f, fmaf(wts[3], Dr3, fmaf(wts[2], Dr2,
                          fmaf(wts[1], Dr1, __fmul_rn(wts[0], Dr0)))));
        } else {
            unsigned off[4] = {
                (unsigned)(y0c * NW + x0c) * 8u,
                (unsigned)(y0c * NW + x1c) * 8u,
                (unsigned)(y1c * NW + x0c) * 8u,
                (unsigned)(y1c * NW + x1c) * 8u };
            float pg[8];
#pragma unroll
            for (int g = 0; g < 8; g++) pg[g] = 0.f;
#pragma unroll
            for (int t = 0; t < 4; t++) {
                float wt = wts[t];
                const float4* tp = base + off[t];
#pragma unroll
                for (int g = 0; g < 8; g++) {
                    float4 q  = __ldg(tp + g);
                    float4 rq = rf_s[wslot][g];
                    float d = fmaf(q.x, rq.x,
                              fmaf(q.y, rq.y,
                              fmaf(q.z, rq.z, __fmul_rn(q.w, rq.w))));
                    pg[g] = fmaf(wt, d, pg[g]);
                }
            }
            s = 0.f; r = 0.f;
#pragma unroll
            for (int g = 0; g < 8; g++) {
                float cfg = __fmul_rn(pg[g], 0.25f);
                float rwg = __shfl_sync(FULL, rw_l, g);
                s = (g == 0) ? cfg : __fadd_rn(s, cfg);
                r = (g == 0) ? __fmul_rn(rwg, cfg) : fmaf(rwg, cfg, r);
            }
        }
        s_v[vi] = s;
        r_v[vi] = r;
    }

    // Per-view softmax accumulation (frozen sequential view order).
    float acc_r = 0.f;
    float cw_sum = 1e-8f;
#pragma unroll
    for (int vi = 0; vi < NV - 1; vi++) {
        float s = s_v[vi];
        float m = warp_bfly_max(s);
        float e = __expf(__fsub_rn(s, m));
        float es = warp_bfly_sum(e);
        float wv = __fmul_rn(__fdiv_rn(e, es), 0.17677669529663687f);  // 1/sqrt(32)
        cw_sum = __fadd_rn(cw_sum, wv);
        acc_r  = fmaf(wv, r_v[vi], acc_r);
    }

    float logit = __fdiv_rn(acc_r, cw_sum);

    // final softmax over depth
    float m2 = warp_bfly_max(logit);
    float e2 = __expf(__fsub_rn(logit, m2));
    float es2 = warp_bfly_sum(e2);
    float attn = __fdiv_rn(e2, es2);

    // depth output (argmax lane)
    float amax = warp_bfly_max(attn);
    unsigned msk = __ballot_sync(FULL, attn == amax);
    int idx = __ffs(msk) - 1;   // first max, matching jnp.argmax
    if (lane == idx) out[(unsigned)b * HW + hw] = dep;

    // attn output: stage through smem, write coalesced (d-major per block).
    attn_s[wslot][lane] = attn;
    __syncthreads();
    int t = threadIdx.x;
    int d = t >> 2;          // 0..31
    int p = t & 3;           // pixel offset within block
    unsigned hw_base = ((unsigned)blockIdx.x * 4) & (HW - 1);
    out[(unsigned)NB * HW + (unsigned)(b * ND + d) * HW + hw_base + p] =
        attn_s[p][d];
}

// ---------------------------------------------------------------------------
// Launch
// ---------------------------------------------------------------------------
extern "C" void kernel_launch(void* const* d_in, const int* in_sizes, int n_in,
                              void* d_out, int out_size) {
    const float* features   = (const float*)d_in[0];
    const float* proj       = (const float*)d_in[1];
    const float* depth_hypo = (const float*)d_in[2];
    const float* reg_w      = (const float*)d_in[3];
    float* out = (float*)d_out;

    prep_kernel<<<dim3(HW / 32, NV * NB + NB), dim3(8, 32)>>>(features, depth_hypo, proj);
    stagenet_main<<<(NB * HW) / 4, 128>>>(reg_w, out);
}

// round 16
// speedup vs baseline: 1.2943x; 1.2943x over previous
#include <cuda_runtime.h>
#include <cstdint>

// Problem constants (stagenet_46445776339346): V=5, B=2, C=32, H=W=128, D=32, G=8
#define NV 5
#define NB 2
#define NC 32
#define NH 128
#define NW 128
#define ND 32
#define NG 8
#define HW (NH * NW)

// ---------------------------------------------------------------------------
// Device scratch (no runtime allocation allowed)
// ---------------------------------------------------------------------------
// packed projection: per (b,v) three float4 rows {R3r, R3r+1, R3r+2, Tr}
__device__ float4 g_proj4[NB][NV][3];
// features transposed to [V, B, H*W, C]: one bilinear tap = 128 contiguous bytes.
__device__ float4 g_featT[(size_t)NV * NB * HW * (NC / 4)];
// depth hypotheses transposed to [B, H*W, D]: one warp load = 128 contiguous B.
__device__ float  g_depT[(size_t)NB * HW * ND];

// ---------------------------------------------------------------------------
// FROZEN NUMERICS: fp32 4x4 inverse = sgetf2 LU + OpenBLAS-style trsm
// (pre-inverted diagonal). Do not touch.
// ---------------------------------------------------------------------------
__device__ void inv4_lapack_f32(const float* A_rm, float* Ai_rm) {
    float a[16];
    int   piv[4];
#pragma unroll
    for (int r = 0; r < 4; r++)
#pragma unroll
        for (int c = 0; c < 4; c++) a[c * 4 + r] = A_rm[r * 4 + c];

#pragma unroll
    for (int j = 0; j < 4; j++) {
        int jp = j; float amax = fabsf(a[j * 4 + j]);
        for (int i = j + 1; i < 4; i++) {
            float v = fabsf(a[j * 4 + i]);
            if (v > amax) { amax = v; jp = i; }
        }
        piv[j] = jp;
        if (jp != j)
#pragma unroll
            for (int c = 0; c < 4; c++) {
                float t = a[c * 4 + j]; a[c * 4 + j] = a[c * 4 + jp]; a[c * 4 + jp] = t;
            }
        float ainv = __fdiv_rn(1.0f, a[j * 4 + j]);
        for (int i = j + 1; i < 4; i++)
            a[j * 4 + i] = __fmul_rn(a[j * 4 + i], ainv);
        for (int k = j + 1; k < 4; k++) {
            float temp = -a[k * 4 + j];
            for (int i = j + 1; i < 4; i++)
                a[k * 4 + i] = fmaf(a[j * 4 + i], temp, a[k * 4 + i]);
        }
    }

    float dinv[4];
#pragma unroll
    for (int k = 0; k < 4; k++) dinv[k] = __fdiv_rn(1.0f, a[k * 4 + k]);

#pragma unroll
    for (int c = 0; c < 4; c++) {
        float b[4] = {0.f, 0.f, 0.f, 0.f};
        b[c] = 1.0f;
#pragma unroll
        for (int j = 0; j < 4; j++) { float t = b[j]; b[j] = b[piv[j]]; b[piv[j]] = t; }
#pragma unroll
        for (int k = 0; k < 4; k++) {
            float bk = b[k];
            if (bk != 0.f)
                for (int i = k + 1; i < 4; i++)
                    b[i] = fmaf(-bk, a[k * 4 + i], b[i]);
        }
#pragma unroll
        for (int k = 3; k >= 0; k--) {
            b[k] = __fmul_rn(b[k], dinv[k]);
            float bk = b[k];
            for (int i = 0; i < k; i++)
                b[i] = fmaf(-bk, a[k * 4 + i], b[i]);
        }
#pragma unroll
        for (int r = 0; r < 4; r++) Ai_rm[r * 4 + c] = b[r];
    }
}

__device__ void make_comb_f32(const float* pm, int b, int v, float* M) {
    const float* ext = pm + ((size_t)(b * NV + v) * 2 + 0) * 16;
    const float* K   = pm + ((size_t)(b * NV + v) * 2 + 1) * 16;
#pragma unroll
    for (int r = 0; r < 3; r++)
#pragma unroll
        for (int c = 0; c < 4; c++) {
            float s = __fmul_rn(K[r * 4 + 0], ext[0 * 4 + c]);
            s = fmaf(K[r * 4 + 1], ext[1 * 4 + c], s);
            s = fmaf(K[r * 4 + 2], ext[2 * 4 + c], s);
            M[r * 4 + c] = s;
        }
#pragma unroll
    for (int c = 0; c < 4; c++) M[12 + c] = ext[12 + c];
}

__device__ void do_setup(const float* pm, int b) {
    float Mr[16], Mi[16];
    make_comb_f32(pm, b, 0, Mr);
    inv4_lapack_f32(Mr, Mi);
    for (int v = 1; v < NV; v++) {
        float Ms[16];
        make_comb_f32(pm, b, v, Ms);
        float* P = (float*)&g_proj4[b][v][0];
        for (int r = 0; r < 3; r++) {
            for (int c = 0; c < 4; c++) {
                float s = __fmul_rn(Ms[r * 4 + 0], Mi[0 * 4 + c]);
                s = fmaf(Ms[r * 4 + 1], Mi[1 * 4 + c], s);
                s = fmaf(Ms[r * 4 + 2], Mi[2 * 4 + c], s);
                s = fmaf(Ms[r * 4 + 3], Mi[3 * 4 + c], s);
                if (c < 3) P[r * 4 + c] = s;
                else       P[r * 4 + 3] = s;
            }
        }
    }
}

// ---------------------------------------------------------------------------
// Prep kernel: 32x32 float4-vectorized transposes (features + depth) +
// projection setup on 2 threads of block (0,0).
// ---------------------------------------------------------------------------
__global__ void prep_kernel(const float* __restrict__ fea,
                            const float* __restrict__ dh,
                            const float* __restrict__ pm) {
    __shared__ float tile[32][33];
    int by = blockIdx.y;
    int pb = blockIdx.x * 32;
    int tx = threadIdx.x;   // 0..7
    int ty = threadIdx.y;   // 0..31

    if (blockIdx.x == 0 && by == 0 && ty == 31 && tx < NB)
        do_setup(pm, tx);

    const float* src;
    float*       dst;
    if (by < NV * NB) {
        src = fea + ((size_t)by * NC + ty) * HW + pb;
        dst = (float*)g_featT + ((size_t)by * HW + pb) * NC;
    } else {
        int b = by - NV * NB;
        src = dh + ((size_t)b * ND + ty) * HW + pb;
        dst = g_depT + ((size_t)b * HW + pb) * ND;
    }

    float4 v = ((const float4*)src)[tx];
    tile[ty][4 * tx + 0] = v.x;
    tile[ty][4 * tx + 1] = v.y;
    tile[ty][4 * tx + 2] = v.z;
    tile[ty][4 * tx + 3] = v.w;
    __syncthreads();

    float4 o;
    o.x = tile[4 * tx + 0][ty];
    o.y = tile[4 * tx + 1][ty];
    o.z = tile[4 * tx + 2][ty];
    o.w = tile[4 * tx + 3][ty];
    ((float4*)(dst + (size_t)ty * 32))[tx] = o;
}

__device__ __forceinline__ float warp_bfly_sum(float x) {
    const unsigned FULL = 0xffffffffu;
#pragma unroll
    for (int o = 16; o; o >>= 1) x = __fadd_rn(x, __shfl_xor_sync(FULL, x, o));
    return x;
}

__device__ __forceinline__ float warp_bfly_max(float x) {
    const unsigned FULL = 0xffffffffu;
#pragma unroll
    for (int o = 16; o; o >>= 1) x = fmaxf(x, __shfl_xor_sync(FULL, x, o));
    return x;
}

// Butterfly sum within each 8-lane group (offsets 1,2,4).
__device__ __forceinline__ float group8_sum(float x) {
    const unsigned FULL = 0xffffffffu;
#pragma unroll
    for (int o = 1; o < 8; o <<= 1) x = __fadd_rn(x, __shfl_xor_sync(FULL, x, o));
    return x;
}

// ---------------------------------------------------------------------------
// Main kernel: one warp per ref pixel, lane = depth hypothesis.
// ---------------------------------------------------------------------------
__global__ void __launch_bounds__(128, 10) stagenet_main(
    const float* __restrict__ reg_w,
    float* __restrict__ out) {
    const unsigned FULL = 0xffffffffu;
    __shared__ float4 rf_s[4][8];
    __shared__ float  attn_s[4][40];   // stride 40: conflict-free both ways

    int warp = blockIdx.x * (blockDim.x >> 5) + (threadIdx.x >> 5);
    int wslot = threadIdx.x >> 5;
    int lane = threadIdx.x & 31;
    int gl   = lane & 7;

    int b  = warp >> 14;
    int hw = warp & (HW - 1);
    int h  = hw >> 7;
    int w  = hw & (NW - 1);

    if (lane < 8)
        rf_s[wslot][lane] = __ldg(g_featT + ((unsigned)b * HW + hw) * 8 + lane);
    __syncwarp();
    float4 rfl = rf_s[wslot][gl];
    float  rw_l = __ldg(reg_w + gl);

    // transposed depth: 32 consecutive floats per warp = 1 cache line
    float dep = g_depT[((unsigned)b * HW + hw) * ND + lane];
    float xw = (float)w, yh = (float)h;

    // Hoist all projection rows (uniform LDG.128s, front-batched for MLP).
    float4 P[NV - 1][3];
#pragma unroll
    for (int vi = 0; vi < NV - 1; vi++) {
        P[vi][0] = g_proj4[b][vi + 1][0];
        P[vi][1] = g_proj4[b][vi + 1][1];
        P[vi][2] = g_proj4[b][vi + 1][2];
    }

    float s_v[NV - 1], r_v[NV - 1];

#pragma unroll
    for (int vi = 0; vi < NV - 1; vi++) {
        int v = vi + 1;
        float4 P0 = P[vi][0], P1 = P[vi][1], P2 = P[vi][2];
        float rx = fmaf(P0.z, 1.f, fmaf(P0.y, yh, __fmul_rn(P0.x, xw)));
        float ry = fmaf(P1.z, 1.f, fmaf(P1.y, yh, __fmul_rn(P1.x, xw)));
        float rz = fmaf(P2.z, 1.f, fmaf(P2.y, yh, __fmul_rn(P2.x, xw)));
        float X = __fadd_rn(__fmul_rn(rx, dep), P0.w);
        float Y = __fadd_rn(__fmul_rn(ry, dep), P1.w);
        float Z = __fadd_rn(__fmul_rn(rz, dep), P2.w);
        if (Z == 0.f) Z = 1e-9f;
        float px = __fdiv_rn(X, Z);
        float py = __fdiv_rn(Y, Z);

        float x0f = floorf(px), y0f = floorf(py);
        int   x0 = (int)x0f,   y0 = (int)y0f;
        float wx1 = __fsub_rn(px, x0f), wx0 = __fsub_rn(1.f, wx1);
        float wy1 = __fsub_rn(py, y0f), wy0 = __fsub_rn(1.f, wy1);

        int x0c = min(max(x0, 0), NW - 1), x1c = min(max(x0 + 1, 0), NW - 1);
        int y0c = min(max(y0, 0), NH - 1), y1c = min(max(y0 + 1, 0), NH - 1);
        bool vx0 = (x0 >= 0) & (x0 < NW),     vx1 = (x0 + 1 >= 0) & (x0 + 1 < NW);
        bool vy0 = (y0 >= 0) & (y0 < NH),     vy1 = (y0 + 1 >= 0) & (y0 + 1 < NH);
        float wts[4] = {
            (vx0 & vy0) ? __fmul_rn(wx0, wy0) : 0.f,
            (vx1 & vy0) ? __fmul_rn(wx1, wy0) : 0.f,
            (vx0 & vy1) ? __fmul_rn(wx0, wy1) : 0.f,
            (vx1 & vy1) ? __fmul_rn(wx1, wy1) : 0.f };
        const float4* base = g_featT + (unsigned)(v * NB + b) * (HW * 8u);

        // single-key uniformity check
        int key = (y0 << 16) ^ (x0 & 0xffff);
        bool uni = __all_sync(FULL, key == __shfl_sync(FULL, key, 0));

        float s, r;
        if (uni) {
            int xc = (lane & 8)  ? x1c : x0c;
            int yc = (lane & 16) ? y1c : y0c;
            float4 q = __ldg(base + (unsigned)(yc * NW + xc) * 8u + (unsigned)gl);
            float d = fmaf(q.x, rfl.x,
                      fmaf(q.y, rfl.y,
                      fmaf(q.z, rfl.z, __fmul_rn(q.w, rfl.w))));
            float D  = group8_sum(d);                       // sum_g d[t,g]
            float Dr = group8_sum(__fmul_rn(rw_l, d));      // sum_g rw_g*d[t,g]
            float D0  = __shfl_sync(FULL, D, 0),  D1  = __shfl_sync(FULL, D, 8);
            float D2  = __shfl_sync(FULL, D, 16), D3  = __shfl_sync(FULL, D, 24);
            float Dr0 = __shfl_sync(FULL, Dr, 0),  Dr1 = __shfl_sync(FULL, Dr, 8);
            float Dr2 = __shfl_sync(FULL, Dr, 16), Dr3 = __shfl_sync(FULL, Dr, 24);
            s = __fmul_rn(0.25f, fmaf(wts[3], D3, fmaf(wts[2], D2,
                          fmaf(wts[1], D1, __fmul_rn(wts[0], D0)))));
            r = __fmul_rn(0.25f, fmaf(wts[3], Dr3, fmaf(wts[2], Dr2,
                          fmaf(wts[1], Dr1, __fmul_rn(wts[0], Dr0)))));
        } else {
            unsigned off[4] = {
                (unsigned)(y0c * NW + x0c) * 8u,
                (unsigned)(y0c * NW + x1c) * 8u,
                (unsigned)(y1c * NW + x0c) * 8u,
                (unsigned)(y1c * NW + x1c) * 8u };
            float pg[8];
#pragma unroll
            for (int g = 0; g < 8; g++) pg[g] = 0.f;
#pragma unroll
            for (int t = 0; t < 4; t++) {
                float wt = wts[t];
                const float4* tp = base + off[t];
#pragma unroll
                for (int g = 0; g < 8; g++) {
                    float4 q  = __ldg(tp + g);
                    float4 rq = rf_s[wslot][g];
                    float d = fmaf(q.x, rq.x,
                              fmaf(q.y, rq.y,
                              fmaf(q.z, rq.z, __fmul_rn(q.w, rq.w))));
                    pg[g] = fmaf(wt, d, pg[g]);
                }
            }
            s = 0.f; r = 0.f;
#pragma unroll
            for (int g = 0; g < 8; g++) {
                float cfg = __fmul_rn(pg[g], 0.25f);
                float rwg = __shfl_sync(FULL, rw_l, g);
                s = (g == 0) ? cfg : __fadd_rn(s, cfg);
                r = (g == 0) ? __fmul_rn(rwg, cfg) : fmaf(rwg, cfg, r);
            }
        }
        s_v[vi] = s;
        r_v[vi] = r;
    }

    // Per-view softmax accumulation (frozen sequential view order).
    float acc_r = 0.f;
    float cw_sum = 1e-8f;
#pragma unroll
    for (int vi = 0; vi < NV - 1; vi++) {
        float s = s_v[vi];
        float m = warp_bfly_max(s);
        float e = __expf(__fsub_rn(s, m));
        float es = warp_bfly_sum(e);
        float wv = __fmul_rn(__fdiv_rn(e, es), 0.17677669529663687f);  // 1/sqrt(32)
        cw_sum = __fadd_rn(cw_sum, wv);
        acc_r  = fmaf(wv, r_v[vi], acc_r);
    }

    float logit = __fdiv_rn(acc_r, cw_sum);

    // final softmax over depth
    float m2 = warp_bfly_max(logit);
    float e2 = __expf(__fsub_rn(logit, m2));
    float es2 = warp_bfly_sum(e2);
    float attn = __fdiv_rn(e2, es2);

    // depth output (argmax lane)
    float amax = warp_bfly_max(attn);
    unsigned msk = __ballot_sync(FULL, attn == amax);
    int idx = __ffs(msk) - 1;   // first max, matching jnp.argmax
    if (lane == idx) out[(unsigned)b * HW + hw] = dep;

    // attn output: stage through smem, write coalesced (d-major per block).
    attn_s[wslot][lane] = attn;
    __syncthreads();
    int t = threadIdx.x;
    int d = t >> 2;          // 0..31
    int p = t & 3;           // pixel offset within block
    unsigned hw_base = ((unsigned)blockIdx.x * 4) & (HW - 1);
    out[(unsigned)NB * HW + (unsigned)(b * ND + d) * HW + hw_base + p] =
        attn_s[p][d];
}

// ---------------------------------------------------------------------------
// Launch
// ---------------------------------------------------------------------------
extern "C" void kernel_launch(void* const* d_in, const int* in_sizes, int n_in,
                              void* d_out, int out_size) {
    const float* features   = (const float*)d_in[0];
    const float* proj       = (const float*)d_in[1];
    const float* depth_hypo = (const float*)d_in[2];
    const float* reg_w      = (const float*)d_in[3];
    float* out = (float*)d_out;

    prep_kernel<<<dim3(HW / 32, NV * NB + NB), dim3(8, 32)>>>(features, depth_hypo, proj);
    stagenet_main<<<(NB * HW) / 4, 128>>>(reg_w, out);
}

// round 17
// speedup vs baseline: 1.6239x; 1.2546x over previous
#include <cuda_runtime.h>
#include <cstdint>

// Problem constants (stagenet_46445776339346): V=5, B=2, C=32, H=W=128, D=32, G=8
#define NV 5
#define NB 2
#define NC 32
#define NH 128
#define NW 128
#define ND 32
#define NG 8
#define HW (NH * NW)

// ---------------------------------------------------------------------------
// Device scratch (no runtime allocation allowed)
// ---------------------------------------------------------------------------
// packed projection: per (b,v) three float4 rows {R3r, R3r+1, R3r+2, Tr}
__device__ float4 g_proj4[NB][NV][3];
// features transposed to [V, B, H*W, C]: one bilinear tap = 128 contiguous bytes.
__device__ float4 g_featT[(size_t)NV * NB * HW * (NC / 4)];
// depth hypotheses transposed to [B, H*W, D].
__device__ float  g_depT[(size_t)NB * HW * ND];

// ---------------------------------------------------------------------------
// FROZEN NUMERICS: fp32 4x4 inverse = sgetf2 LU + OpenBLAS-style trsm
// (pre-inverted diagonal). Do not touch.
// ---------------------------------------------------------------------------
__device__ void inv4_lapack_f32(const float* A_rm, float* Ai_rm) {
    float a[16];
    int   piv[4];
#pragma unroll
    for (int r = 0; r < 4; r++)
#pragma unroll
        for (int c = 0; c < 4; c++) a[c * 4 + r] = A_rm[r * 4 + c];

#pragma unroll
    for (int j = 0; j < 4; j++) {
        int jp = j; float amax = fabsf(a[j * 4 + j]);
        for (int i = j + 1; i < 4; i++) {
            float v = fabsf(a[j * 4 + i]);
            if (v > amax) { amax = v; jp = i; }
        }
        piv[j] = jp;
        if (jp != j)
#pragma unroll
            for (int c = 0; c < 4; c++) {
                float t = a[c * 4 + j]; a[c * 4 + j] = a[c * 4 + jp]; a[c * 4 + jp] = t;
            }
        float ainv = __fdiv_rn(1.0f, a[j * 4 + j]);
        for (int i = j + 1; i < 4; i++)
            a[j * 4 + i] = __fmul_rn(a[j * 4 + i], ainv);
        for (int k = j + 1; k < 4; k++) {
            float temp = -a[k * 4 + j];
            for (int i = j + 1; i < 4; i++)
                a[k * 4 + i] = fmaf(a[j * 4 + i], temp, a[k * 4 + i]);
        }
    }

    float dinv[4];
#pragma unroll
    for (int k = 0; k < 4; k++) dinv[k] = __fdiv_rn(1.0f, a[k * 4 + k]);

#pragma unroll
    for (int c = 0; c < 4; c++) {
        float b[4] = {0.f, 0.f, 0.f, 0.f};
        b[c] = 1.0f;
#pragma unroll
        for (int j = 0; j < 4; j++) { float t = b[j]; b[j] = b[piv[j]]; b[piv[j]] = t; }
#pragma unroll
        for (int k = 0; k < 4; k++) {
            float bk = b[k];
            if (bk != 0.f)
                for (int i = k + 1; i < 4; i++)
                    b[i] = fmaf(-bk, a[k * 4 + i], b[i]);
        }
#pragma unroll
        for (int k = 3; k >= 0; k--) {
            b[k] = __fmul_rn(b[k], dinv[k]);
            float bk = b[k];
            for (int i = 0; i < k; i++)
                b[i] = fmaf(-bk, a[k * 4 + i], b[i]);
        }
#pragma unroll
        for (int r = 0; r < 4; r++) Ai_rm[r * 4 + c] = b[r];
    }
}

__device__ void make_comb_f32(const float* pm, int b, int v, float* M) {
    const float* ext = pm + ((size_t)(b * NV + v) * 2 + 0) * 16;
    const float* K   = pm + ((size_t)(b * NV + v) * 2 + 1) * 16;
#pragma unroll
    for (int r = 0; r < 3; r++)
#pragma unroll
        for (int c = 0; c < 4; c++) {
            float s = __fmul_rn(K[r * 4 + 0], ext[0 * 4 + c]);
            s = fmaf(K[r * 4 + 1], ext[1 * 4 + c], s);
            s = fmaf(K[r * 4 + 2], ext[2 * 4 + c], s);
            M[r * 4 + c] = s;
        }
#pragma unroll
    for (int c = 0; c < 4; c++) M[12 + c] = ext[12 + c];
}

__device__ void do_setup(const float* pm, int b) {
    float Mr[16], Mi[16];
    make_comb_f32(pm, b, 0, Mr);
    inv4_lapack_f32(Mr, Mi);
    for (int v = 1; v < NV; v++) {
        float Ms[16];
        make_comb_f32(pm, b, v, Ms);
        float* P = (float*)&g_proj4[b][v][0];
        for (int r = 0; r < 3; r++) {
            for (int c = 0; c < 4; c++) {
                float s = __fmul_rn(Ms[r * 4 + 0], Mi[0 * 4 + c]);
                s = fmaf(Ms[r * 4 + 1], Mi[1 * 4 + c], s);
                s = fmaf(Ms[r * 4 + 2], Mi[2 * 4 + c], s);
                s = fmaf(Ms[r * 4 + 3], Mi[3 * 4 + c], s);
                if (c < 3) P[r * 4 + c] = s;
                else       P[r * 4 + 3] = s;
            }
        }
    }
}

// ---------------------------------------------------------------------------
// Prep kernel: 32x32 float4-vectorized transposes (features + depth) +
// projection setup on 2 threads of block (0,0).
// ---------------------------------------------------------------------------
__global__ void prep_kernel(const float* __restrict__ fea,
                            const float* __restrict__ dh,
                            const float* __restrict__ pm) {
    __shared__ float tile[32][33];
    int by = blockIdx.y;
    int pb = blockIdx.x * 32;
    int tx = threadIdx.x;   // 0..7
    int ty = threadIdx.y;   // 0..31

    if (blockIdx.x == 0 && by == 0 && ty == 31 && tx < NB)
        do_setup(pm, tx);

    const float* src;
    float*       dst;
    if (by < NV * NB) {
        src = fea + ((size_t)by * NC + ty) * HW + pb;
        dst = (float*)g_featT + ((size_t)by * HW + pb) * NC;
    } else {
        int b = by - NV * NB;
        src = dh + ((size_t)b * ND + ty) * HW + pb;
        dst = g_depT + ((size_t)b * HW + pb) * ND;
    }

    float4 v = ((const float4*)src)[tx];
    tile[ty][4 * tx + 0] = v.x;
    tile[ty][4 * tx + 1] = v.y;
    tile[ty][4 * tx + 2] = v.z;
    tile[ty][4 * tx + 3] = v.w;
    __syncthreads();

    float4 o;
    o.x = tile[4 * tx + 0][ty];
    o.y = tile[4 * tx + 1][ty];
    o.z = tile[4 * tx + 2][ty];
    o.w = tile[4 * tx + 3][ty];
    ((float4*)(dst + (size_t)ty * 32))[tx] = o;
}

__device__ __forceinline__ float warp_bfly_sum(float x) {
    const unsigned FULL = 0xffffffffu;
#pragma unroll
    for (int o = 16; o; o >>= 1) x = __fadd_rn(x, __shfl_xor_sync(FULL, x, o));
    return x;
}

__device__ __forceinline__ float warp_bfly_max(float x) {
    const unsigned FULL = 0xffffffffu;
#pragma unroll
    for (int o = 16; o; o >>= 1) x = fmaxf(x, __shfl_xor_sync(FULL, x, o));
    return x;
}

// Butterfly sum within each 8-lane group (offsets 1,2,4).
__device__ __forceinline__ float group8_sum(float x) {
    const unsigned FULL = 0xffffffffu;
#pragma unroll
    for (int o = 1; o < 8; o <<= 1) x = __fadd_rn(x, __shfl_xor_sync(FULL, x, o));
    return x;
}

// ---------------------------------------------------------------------------
// Main kernel: one warp per ref pixel, lane = depth hypothesis.
// Projection rows loaded in-loop (NOT hoisted: front-batched uniform LDGs
// were shown in R16 to congest the L1 queue ahead of the tap loads).
// Softmax divisions use __fdividef (MUFU.RCP+mul); logit division stays
// precise (feeds argmax).
// ---------------------------------------------------------------------------
__global__ void __launch_bounds__(128, 10) stagenet_main(
    const float* __restrict__ reg_w,
    float* __restrict__ out) {
    const unsigned FULL = 0xffffffffu;
    __shared__ float4 rf_s[4][8];
    __shared__ float  attn_s[4][40];   // stride 40: conflict-free both ways

    int warp = blockIdx.x * (blockDim.x >> 5) + (threadIdx.x >> 5);
    int wslot = threadIdx.x >> 5;
    int lane = threadIdx.x & 31;
    int gl   = lane & 7;

    int b  = warp >> 14;
    int hw = warp & (HW - 1);
    int h  = hw >> 7;
    int w  = hw & (NW - 1);

    if (lane < 8)
        rf_s[wslot][lane] = __ldg(g_featT + ((unsigned)b * HW + hw) * 8 + lane);
    __syncwarp();
    float4 rfl = rf_s[wslot][gl];
    float  rw_l = __ldg(reg_w + gl);

    // transposed depth: 32 consecutive floats per warp = 1 cache line
    float dep = g_depT[((unsigned)b * HW + hw) * ND + lane];
    float xw = (float)w, yh = (float)h;

    float s_v[NV - 1], r_v[NV - 1];

#pragma unroll
    for (int vi = 0; vi < NV - 1; vi++) {
        int v = vi + 1;
        // packed projection rows: {R0,R1,R2,T0} {R3,R4,R5,T1} {R6,R7,R8,T2}
        float4 P0 = g_proj4[b][v][0];
        float4 P1 = g_proj4[b][v][1];
        float4 P2 = g_proj4[b][v][2];
        float rx = fmaf(P0.z, 1.f, fmaf(P0.y, yh, __fmul_rn(P0.x, xw)));
        float ry = fmaf(P1.z, 1.f, fmaf(P1.y, yh, __fmul_rn(P1.x, xw)));
        float rz = fmaf(P2.z, 1.f, fmaf(P2.y, yh, __fmul_rn(P2.x, xw)));
        float X = __fadd_rn(__fmul_rn(rx, dep), P0.w);
        float Y = __fadd_rn(__fmul_rn(ry, dep), P1.w);
        float Z = __fadd_rn(__fmul_rn(rz, dep), P2.w);
        if (Z == 0.f) Z = 1e-9f;
        float px = __fdiv_rn(X, Z);
        float py = __fdiv_rn(Y, Z);

        float x0f = floorf(px), y0f = floorf(py);
        int   x0 = (int)x0f,   y0 = (int)y0f;
        float wx1 = __fsub_rn(px, x0f), wx0 = __fsub_rn(1.f, wx1);
        float wy1 = __fsub_rn(py, y0f), wy0 = __fsub_rn(1.f, wy1);

        int x0c = min(max(x0, 0), NW - 1), x1c = min(max(x0 + 1, 0), NW - 1);
        int y0c = min(max(y0, 0), NH - 1), y1c = min(max(y0 + 1, 0), NH - 1);
        bool vx0 = (x0 >= 0) & (x0 < NW),     vx1 = (x0 + 1 >= 0) & (x0 + 1 < NW);
        bool vy0 = (y0 >= 0) & (y0 < NH),     vy1 = (y0 + 1 >= 0) & (y0 + 1 < NH);
        float wts[4] = {
            (vx0 & vy0) ? __fmul_rn(wx0, wy0) : 0.f,
            (vx1 & vy0) ? __fmul_rn(wx1, wy0) : 0.f,
            (vx0 & vy1) ? __fmul_rn(wx0, wy1) : 0.f,
            (vx1 & vy1) ? __fmul_rn(wx1, wy1) : 0.f };
        const float4* base = g_featT + (unsigned)(v * NB + b) * (HW * 8u);

        // single-key uniformity check
        int key = (y0 << 16) ^ (x0 & 0xffff);
        bool uni = __all_sync(FULL, key == __shfl_sync(FULL, key, 0));

        float s, r;
        if (uni) {
            int xc = (lane & 8)  ? x1c : x0c;
            int yc = (lane & 16) ? y1c : y0c;
            float4 q = __ldg(base + (unsigned)(yc * NW + xc) * 8u + (unsigned)gl);
            float d = fmaf(q.x, rfl.x,
                      fmaf(q.y, rfl.y,
                      fmaf(q.z, rfl.z, __fmul_rn(q.w, rfl.w))));
            float D  = group8_sum(d);                       // sum_g d[t,g]
            float Dr = group8_sum(__fmul_rn(rw_l, d));      // sum_g rw_g*d[t,g]
            float D0  = __shfl_sync(FULL, D, 0),  D1  = __shfl_sync(FULL, D, 8);
            float D2  = __shfl_sync(FULL, D, 16), D3  = __shfl_sync(FULL, D, 24);
            float Dr0 = __shfl_sync(FULL, Dr, 0),  Dr1 = __shfl_sync(FULL, Dr, 8);
            float Dr2 = __shfl_sync(FULL, Dr, 16), Dr3 = __shfl_sync(FULL, Dr, 24);
            s = __fmul_rn(0.25f, fmaf(wts[3], D3, fmaf(wts[2], D2,
                          fmaf(wts[1], D1, __fmul_rn(wts[0], D0)))));
            r = __fmul_rn(0.25f, fmaf(wts[3], Dr3, fmaf(wts[2], Dr2,
                          fmaf(wts[1], Dr1, __fmul_rn(wts[0], Dr0)))));
        } else {
            unsigned off[4] = {
                (unsigned)(y0c * NW + x0c) * 8u,
                (unsigned)(y0c * NW + x1c) * 8u,
                (unsigned)(y1c * NW + x0c) * 8u,
                (unsigned)(y1c * NW + x1c) * 8u };
            float pg[8];
#pragma unroll
            for (int g = 0; g < 8; g++) pg[g] = 0.f;
#pragma unroll
            for (int t = 0; t < 4; t++) {
                float wt = wts[t];
                const float4* tp = base + off[t];
#pragma unroll
                for (int g = 0; g < 8; g++) {
                    float4 q  = __ldg(tp + g);
                    float4 rq = rf_s[wslot][g];
                    float d = fmaf(q.x, rq.x,
                              fmaf(q.y, rq.y,
                              fmaf(q.z, rq.z, __fmul_rn(q.w, rq.w))));
                    pg[g] = fmaf(wt, d, pg[g]);
                }
            }
            s = 0.f; r = 0.f;
#pragma unroll
            for (int g = 0; g < 8; g++) {
                float cfg = __fmul_rn(pg[g], 0.25f);
                float rwg = __shfl_sync(FULL, rw_l, g);
                s = (g == 0) ? cfg : __fadd_rn(s, cfg);
                r = (g == 0) ? __fmul_rn(rwg, cfg) : fmaf(rwg, cfg, r);
            }
        }
        s_v[vi] = s;
        r_v[vi] = r;
    }

    // Per-view softmax accumulation (frozen sequential view order).
    float acc_r = 0.f;
    float cw_sum = 1e-8f;
#pragma unroll
    for (int vi = 0; vi < NV - 1; vi++) {
        float s = s_v[vi];
        float m = warp_bfly_max(s);
        float e = __expf(__fsub_rn(s, m));
        float es = warp_bfly_sum(e);
        float wv = __fmul_rn(__fdividef(e, es), 0.17677669529663687f);  // 1/sqrt(32)
        cw_sum = __fadd_rn(cw_sum, wv);
        acc_r  = fmaf(wv, r_v[vi], acc_r);
    }

    float logit = __fdiv_rn(acc_r, cw_sum);   // precise: feeds argmax

    // final softmax over depth
    float m2 = warp_bfly_max(logit);
    float e2 = __expf(__fsub_rn(logit, m2));
    float es2 = warp_bfly_sum(e2);
    float attn = __fdividef(e2, es2);

    // depth output (argmax lane)
    float amax = warp_bfly_max(attn);
    unsigned msk = __ballot_sync(FULL, attn == amax);
    int idx = __ffs(msk) - 1;   // first max, matching jnp.argmax
    if (lane == idx) out[(unsigned)b * HW + hw] = dep;

    // attn output: stage through smem, write coalesced (d-major per block).
    attn_s[wslot][lane] = attn;
    __syncthreads();
    int t = threadIdx.x;
    int d = t >> 2;          // 0..31
    int p = t & 3;           // pixel offset within block
    unsigned hw_base = ((unsigned)blockIdx.x * 4) & (HW - 1);
    out[(unsigned)NB * HW + (unsigned)(b * ND + d) * HW + hw_base + p] =
        attn_s[p][d];
}

// ---------------------------------------------------------------------------
// Launch
// ---------------------------------------------------------------------------
extern "C" void kernel_launch(void* const* d_in, const int* in_sizes, int n_in,
                              void* d_out, int out_size) {
    const float* features   = (const float*)d_in[0];
    const float* proj       = (const float*)d_in[1];
    const float* depth_hypo = (const float*)d_in[2];
    const float* reg_w      = (const float*)d_in[3];
    float* out = (float*)d_out;

    prep_kernel<<<dim3(HW / 32, NV * NB + NB), dim3(8, 32)>>>(features, depth_hypo, proj);
    stagenet_main<<<(NB * HW) / 4, 128>>>(reg_w, out);
}